// round 14
// baseline (speedup 1.0000x reference)
#include <cuda_runtime.h>
#include <cstdint>
#include <climits>

// ============================================================================
// Quantized VGG forward (batch 512) — integer levels end-to-end.
// Convs 1-12: IMMA m16n8k32 (s8 x u8 -> s32, exact), fragment-ordered weights,
// K-chunk 64, warp tiles up to 64x64, channel-interleaved activations (LDS.64
// B fragments). Epilogue: integer THRESHOLD quantization (bit-identical to the
// fp64 rint factor, but fp64-free). rel_err must stay exactly 0.0.
// ============================================================================

#define BATCH 512
#define NLAYERS 13

#define ACT8_ELEMS (512*64*32*32)
#define WQ8_WORDS  4000000

__device__ __align__(256) uint8_t g_act8A[ACT8_ELEMS];
__device__ __align__(256) uint8_t g_act8B[ACT8_ELEMS];
__device__ float   g_fc0[BATCH * 512];
__device__ float   g_fcA[BATCH * 512];
__device__ float   g_fcB[BATCH * 512];
__device__ float   g_wq0[32 * 64];
__device__ __align__(256) int g_wq8[WQ8_WORDS];
__device__ double  g_partial[NLAYERS * 256];
__device__ float   g_scale[NLAYERS * 2];
__device__ int     g_thr[NLAYERS * 32];      // per layer: t[0..16], t[0]=-inf,t[16]=+inf
__device__ float   g_Ff[NLAYERS];            // fp32 copy of F for the guess

struct AbsArgs  { const float* p[13]; int n[13]; };
struct PackArgs { const float* w[12]; long off[12]; int cin[12]; int cout[12];
                  int coutp[12]; int sh[12]; int nwords[12]; };

// Channel permutation: within each 32-channel group, logical word lw stored at
// position s(lw) = ((lw&3)<<1)|(lw>>2)  (storage order holds [0,4,1,5,2,6,3,7]).
__device__ __forceinline__ int sigma_ch(int c) {
    int lw = (c >> 2) & 7;
    int s  = ((lw & 3) << 1) | (lw >> 2);
    return (c & ~31) + s * 4 + (c & 3);
}

// ----------------------------------------------------------------------------
// asm helpers
// ----------------------------------------------------------------------------
__device__ __forceinline__ void cp16(uint32_t saddr, const void* g, unsigned sz) {
    asm volatile("cp.async.cg.shared.global [%0], [%1], 16, %2;"
                 :: "r"(saddr), "l"(g), "r"(sz) : "memory");
}
__device__ __forceinline__ void cp_commit() {
    asm volatile("cp.async.commit_group;" ::: "memory");
}
__device__ __forceinline__ void cp_wait0() {
    asm volatile("cp.async.wait_group 0;" ::: "memory");
}
__device__ __forceinline__ void imma16832(int* c, const int* a, const unsigned* b) {
    asm volatile(
        "mma.sync.aligned.m16n8k32.row.col.s32.s8.u8.s32 "
        "{%0,%1,%2,%3}, {%4,%5,%6,%7}, {%8,%9}, {%0,%1,%2,%3};"
        : "+r"(c[0]), "+r"(c[1]), "+r"(c[2]), "+r"(c[3])
        : "r"(a[0]), "r"(a[1]), "r"(a[2]), "r"(a[3]),
          "r"(b[0]), "r"(b[1]));
}

// ----------------------------------------------------------------------------
// Fused prep (identical reduction order -> same scale bits as R6-R13)
// ----------------------------------------------------------------------------
__global__ void absum_all_kernel(AbsArgs aa, double* __restrict__ partial) {
    int layer = blockIdx.y;
    const float* w = aa.p[layer];
    int n = aa.n[layer];
    __shared__ double s[256];
    double acc = 0.0;
    for (int i = blockIdx.x * 256 + threadIdx.x; i < n; i += 256 * 256)
        acc += (double)fabsf(w[i]);
    s[threadIdx.x] = acc;
    __syncthreads();
    for (int o = 128; o > 0; o >>= 1) {
        if (threadIdx.x < o) s[threadIdx.x] += s[threadIdx.x + o];
        __syncthreads();
    }
    if (threadIdx.x == 0) partial[layer * 256 + blockIdx.x] = s[0];
}

__global__ void finalize_all_kernel(AbsArgs aa, const double* __restrict__ partial,
                                    float* __restrict__ scale_out) {
    int layer = blockIdx.x;
    __shared__ double s[256];
    s[threadIdx.x] = partial[layer * 256 + threadIdx.x];
    __syncthreads();
    for (int o = 128; o > 0; o >>= 1) {
        if (threadIdx.x < o) s[threadIdx.x] += s[threadIdx.x + o];
        __syncthreads();
    }
    if (threadIdx.x == 0) {
        float sum_f = (float)s[0];
        float mean  = __fdiv_rn(sum_f, (float)aa.n[layer]);
        float alpha = 2.0f * mean;
        float sw    = __fdiv_rn(7.0f, alpha);
        scale_out[layer * 2 + 0] = alpha;
        scale_out[layer * 2 + 1] = sw;
    }
}

// Per-layer quant thresholds: t[k] = min integer S with rint((double)S*F) >= k,
// using EXACTLY the fp64 F expression the verified epilogue used.
__global__ void thr_kernel(const float* __restrict__ alphas,
                           const float* __restrict__ scale,
                           int* __restrict__ thr, float* __restrict__ Ff) {
    int layer = blockIdx.x + 1;             // 1..12
    int k = threadIdx.x;                    // 0..16
    int* T = thr + layer * 32;
    const float alpha_a = alphas[layer];
    const float s_w     = scale[2 * layer + 1];
    const float alpha_p = alphas[layer - 1];
    const double F = (15.0 / (double)alpha_a) / ((double)s_w * (15.0 / (double)alpha_p));
    if (k == 0) { T[0] = INT_MIN; Ff[layer] = (float)F; return; }
    if (k == 16) { T[16] = INT_MAX; return; }
    long lo = -(1L << 24), hi = (1L << 24);
    while (lo < hi) {
        long mid = (lo + hi) >> 1;
        double td = (double)mid * F;
        if (rint(td) >= (double)k) hi = mid; else lo = mid + 1;
    }
    T[k] = (int)lo;
}

__global__ void quantw0_kernel(const float* __restrict__ w, int n, int K, int Cout,
                               const float* __restrict__ scale_p, float* __restrict__ wq_t) {
    int idx = blockIdx.x * blockDim.x + threadIdx.x;
    if (idx >= n) return;
    float alpha = scale_p[0];
    float s     = scale_p[1];
    float wc = fminf(fmaxf(w[idx], -alpha), alpha);
    float m  = rintf(wc * s);
    int mo = idx / K;
    int k  = idx - mo * K;
    wq_t[k * Cout + mo] = m;
}

// Fragment-ordered pack, LOGICAL k4 mapping (R13-verified).
__global__ void pack_frag_kernel(PackArgs pa, const float* __restrict__ scale,
                                 int* __restrict__ wq8) {
    int layer = blockIdx.y;
    int nw = pa.nwords[layer];
    int idx = blockIdx.x * 256 + threadIdx.x;
    if (idx >= nw) return;
    int q    = idx & 3;
    int lane = (idx >> 2) & 31;
    int blk  = idx >> 7;
    int nrb  = pa.coutp[layer] >> 4;
    int kt   = blk / nrb;
    int rblk = blk - kt * nrb;
    int gid = lane >> 2, tig = lane & 3;
    int row = rblk * 16 + ((q & 1) << 3) + gid;
    int k4  = kt * 8 + ((q >> 1) << 2) + tig;       // logical channel-word
    int val = 0;
    int COUT = pa.cout[layer];
    if (row < COUT) {
        int CIN = pa.cin[layer];
        int sh = pa.sh[layer];
        int cmask = (1 << sh) - 1;
        int rs = k4 >> sh;
        int ci0 = (k4 & cmask) << 2;                // logical channel base
        int r = rs / 3, s2 = rs - r * 3;
        float alpha = scale[(layer + 1) * 2 + 0];
        float s     = scale[(layer + 1) * 2 + 1];
        const float* w = pa.w[layer];
        unsigned pack = 0;
        #pragma unroll
        for (int t = 0; t < 4; t++) {
            int ci = ci0 + t;
            float v = w[((row * CIN + ci) * 3 + r) * 3 + s2];
            float wc = fminf(fmaxf(v, -alpha), alpha);
            int mi = (int)rintf(wc * s);
            pack |= ((unsigned)(mi & 0xFF)) << (8 * t);
        }
        val = (int)pack;
    }
    wq8[pa.off[layer] + idx] = val;
}

// ----------------------------------------------------------------------------
// Layer 0 conv: fp32 GEMM (K=27), tile 64x256; fp64 epilogue (S is float here).
// ----------------------------------------------------------------------------
__global__ __launch_bounds__(256) void conv0_kernel(
    const float* __restrict__ x, const float* __restrict__ wq_t,
    uint8_t* __restrict__ out,
    const float* __restrict__ alphas, const float* __restrict__ scale_p)
{
    const int CIN = 3, COUT = 64, H = 32, W = 32, HW = 1024;
    const int K = 27;

    __shared__ float As[8][64];
    __shared__ float Bs[8][256];

    const int t = threadIdx.x;
    const int bx = blockIdx.x;

    const int jcol0 = bx * 256 + t;
    const int n0 = jcol0 >> 10;
    const int rem0 = jcol0 & 1023;
    const int y0 = rem0 >> 5;
    const int x0 = rem0 & 31;
    const float* inbase = x + (size_t)n0 * CIN * HW;

    float acc[8][8];
    #pragma unroll
    for (int i = 0; i < 8; i++)
        #pragma unroll
        for (int j = 0; j < 8; j++) acc[i][j] = 0.f;

    const int tm0 = (t & 7) * 8;
    const int tn0 = (t >> 3) * 8;

    for (int kt = 0; kt < 4; ++kt) {
        const int kbase = kt * 8;
        #pragma unroll
        for (int u = 0; u < 2; u++) {
            int idx = t * 2 + u;
            int col = idx & 63;
            int kk  = idx >> 6;
            int kg = kbase + kk;
            As[kk][col] = (kg < K) ? wq_t[kg * COUT + col] : 0.f;
        }
        #pragma unroll
        for (int u = 0; u < 8; u++) {
            int kg = kbase + u;
            float v = 0.f;
            if (kg < K) {
                int ci = kg / 9;
                int rs = kg - ci * 9;
                int r = rs / 3;
                int s2 = rs - r * 3;
                int yy = y0 + r - 1;
                int xx = x0 + s2 - 1;
                if (yy >= 0 && yy < H && xx >= 0 && xx < W)
                    v = inbase[ci * HW + yy * W + xx];
            }
            Bs[u][t] = v;
        }
        __syncthreads();
        #pragma unroll
        for (int kk = 0; kk < 8; kk++) {
            float a[8], b[8];
            #pragma unroll
            for (int i = 0; i < 8; i++) a[i] = As[kk][tm0 + i];
            #pragma unroll
            for (int j = 0; j < 8; j++) b[j] = Bs[kk][tn0 + j];
            #pragma unroll
            for (int i = 0; i < 8; i++)
                #pragma unroll
                for (int j = 0; j < 8; j++)
                    acc[i][j] = fmaf(a[i], b[j], acc[i][j]);
        }
        __syncthreads();
    }

    const float alpha_a = __ldg(&alphas[0]);
    const float s_w     = scale_p[1];
    const double F = (15.0 / (double)alpha_a) / (double)s_w;

    #pragma unroll
    for (int i = 0; i < 8; i++) {
        int m = tm0 + i;
        int ms = sigma_ch(m);
        #pragma unroll
        for (int j = 0; j < 8; j++) {
            int jj = bx * 256 + tn0 + j;
            int n2 = jj >> 10;
            int rm = jj & 1023;
            int yy = rm >> 5, xx = rm & 31;
            double td = (double)acc[i][j] * F;
            float tq = (float)rint(td);
            tq = fminf(fmaxf(tq, 0.f), 15.f);
            out[(((size_t)n2 * H + yy) * W + xx) * COUT + ms] = (uint8_t)tq;
        }
    }
}

// ----------------------------------------------------------------------------
// IMMA conv, K-chunk 16 packed words, LDS.64 B fragments; integer-threshold
// epilogue (fp64-free, bit-identical to the fp64 rint quantizer).
// ----------------------------------------------------------------------------
template<int NBLK, int WM, int WN>
__global__ __launch_bounds__(256) void conv_frag_kernel(
    const uint8_t* __restrict__ in, const int* __restrict__ wfrag,
    uint8_t* __restrict__ out, int CIN, int COUT, int H, int sh, int COUTP,
    int hwsh, int wsh,
    const int* __restrict__ thr, const float* __restrict__ Ffp, int layer)
{
    constexpr int WROWS = 128 / WM;
    constexpr int AM = WROWS / 16;
    constexpr int NW = NBLK / WN;
    constexpr int AN = NW / 8;
    constexpr int TPP = 256 / NBLK;
    constexpr int QPT = 4 / TPP;
    constexpr int ASTAGE = 2048;
    constexpr int BSTRIDE = 24;

    const int W = H, HW = H * H;
    const int hwmask = HW - 1, wmask = W - 1;
    const int K4 = (CIN * 9) >> 2;
    const int KT = K4 >> 4;
    const int cmask = (1 << sh) - 1;
    const int nrb = COUTP >> 4;

    extern __shared__ char smem[];
    int*      Asm = (int*)smem;
    unsigned* Bsm = (unsigned*)(smem + 2 * ASTAGE * 4);

    const int t = threadIdx.x;
    const int bx = blockIdx.x, by = blockIdx.y;
    const int lane = t & 31;
    const int wid  = t >> 5;
    const int gid  = lane >> 2;
    const int tig  = lane & 3;
    const int warp_m = wid / WN;
    const int warp_n = wid - warp_m * WN;

    const int p  = t % NBLK;
    const int qb = (t / NBLK) * QPT;
    int bn, byy, bxx;
    {
        int jcol = bx * NBLK + p;
        bn  = jcol >> hwsh;
        int rem = jcol & hwmask;
        byy = rem >> wsh;
        bxx = rem & wmask;
    }
    const int arblk = t >> 5;
    const int aoff  = (t & 31) * 4;

    uint32_t sAb = (uint32_t)__cvta_generic_to_shared(Asm);
    uint32_t sBb = (uint32_t)__cvta_generic_to_shared(Bsm);

    int c[AM][AN][4];
    #pragma unroll
    for (int am = 0; am < AM; am++)
        #pragma unroll
        for (int an = 0; an < AN; an++)
            #pragma unroll
            for (int q = 0; q < 4; q++) c[am][an][q] = 0;

    auto load_stage = [&](int kt2, int buf) {
        #pragma unroll
        for (int h = 0; h < 2; h++) {
            const int* ga = wfrag + ((long)(kt2 * 2 + h) * nrb + by * 8 + arblk) * 128 + aoff;
            cp16(sAb + (uint32_t)(buf * ASTAGE + h * 1024 + t * 4) * 4, ga, 16);
        }
        int kg0 = kt2 * 16;
        int rs = kg0 >> sh;
        int ci0 = (kg0 & cmask) << 2;
        int r = rs / 3, s2 = rs - r * 3;
        int yy = byy + r - 1;
        int xx = bxx + s2 - 1;
        bool ok = (yy >= 0 && yy < H && xx >= 0 && xx < W);
        const uint8_t* gb = ok ? in + ((size_t)bn * HW + (size_t)yy * W + xx) * CIN + ci0
                               : in;
        #pragma unroll
        for (int j = 0; j < QPT; j++) {
            int q = qb + j;
            cp16(sBb + (uint32_t)(buf * NBLK * BSTRIDE + p * BSTRIDE + q * 4) * 4,
                 gb + q * 16, ok ? 16u : 0u);
        }
        cp_commit();
    };

    load_stage(0, 0);

    for (int kt2 = 0; kt2 < KT; ++kt2) {
        const int buf = kt2 & 1;
        cp_wait0();
        __syncthreads();
        if (kt2 + 1 < KT) load_stage(kt2 + 1, buf ^ 1);

        const int*      Ab = Asm + buf * ASTAGE;
        const unsigned* Bb = Bsm + buf * NBLK * BSTRIDE;

        #pragma unroll
        for (int h = 0; h < 2; h++) {
            int a[AM][4];
            #pragma unroll
            for (int am = 0; am < AM; am++) {
                const int4 v = *reinterpret_cast<const int4*>(
                    &Ab[h * 1024 + (warp_m * AM + am) * 128 + lane * 4]);
                a[am][0] = v.x; a[am][1] = v.y; a[am][2] = v.z; a[am][3] = v.w;
            }
            unsigned b[AN][2];
            #pragma unroll
            for (int an = 0; an < AN; an++) {
                int pix = warp_n * NW + an * 8 + gid;
                const uint2 v = *reinterpret_cast<const uint2*>(
                    &Bb[pix * BSTRIDE + h * 8 + 2 * tig]);
                b[an][0] = v.x;
                b[an][1] = v.y;
            }
            #pragma unroll
            for (int am = 0; am < AM; am++)
                #pragma unroll
                for (int an = 0; an < AN; an++)
                    imma16832(c[am][an], a[am], b[an]);
        }
        __syncthreads();
    }

    // Integer-threshold epilogue (exact): q s.t. T[q] <= S < T[q+1]
    const int* T = thr + layer * 32;
    const float Ff = __ldg(&Ffp[layer]);
    int Tl[17];
    #pragma unroll
    for (int k = 0; k < 17; k++) Tl[k] = __ldg(&T[k]);

    #pragma unroll
    for (int am = 0; am < AM; am++) {
        int row0 = by * 128 + warp_m * WROWS + am * 16 + gid;
        #pragma unroll
        for (int an = 0; an < AN; an++) {
            int colb = bx * NBLK + warp_n * NW + an * 8 + 2 * tig;
            #pragma unroll
            for (int q2 = 0; q2 < 4; q2++) {
                int row = row0 + (q2 >> 1) * 8;
                int col = colb + (q2 & 1);
                if (row >= COUT) continue;
                int n2 = col >> hwsh;
                int rm = col & hwmask;
                int yy = rm >> wsh, xx = rm & wmask;
                int S = c[am][an][q2];
                int g = (int)fmaf((float)S, Ff, 0.5f);
                g = max(0, min(15, g));
                if (S >= Tl[g + 1]) g++;
                else if (S < Tl[g]) g--;
                out[(((size_t)n2 * H + yy) * W + xx) * COUT + sigma_ch(row)] = (uint8_t)g;
            }
        }
    }
}

// ----------------------------------------------------------------------------
// Pools
// ----------------------------------------------------------------------------
__global__ void pool8_kernel(const uint8_t* __restrict__ in, uint8_t* __restrict__ out,
                             int C, int Hin) {
    int Hout = Hin >> 1;
    int total = BATCH * Hout * Hout * C;
    int idx = blockIdx.x * blockDim.x + threadIdx.x;
    if (idx >= total) return;
    int c = idx % C;
    int tmp = idx / C;
    int x = tmp % Hout;
    tmp /= Hout;
    int y = tmp % Hout;
    int n = tmp / Hout;
    const uint8_t* p = in + (((size_t)n * Hin + 2 * y) * Hin + 2 * x) * C + c;
    size_t rows = (size_t)Hin * C;
    uint8_t v0 = p[0], v1 = p[C], v2 = p[rows], v3 = p[rows + C];
    uint8_t v = v0 > v1 ? v0 : v1;
    uint8_t w = v2 > v3 ? v2 : v3;
    out[idx] = v > w ? v : w;
}

__global__ void pool_final_kernel(const uint8_t* __restrict__ in, float* __restrict__ out,
                                  const float* __restrict__ alphas) {
    int total = BATCH * 512;
    int idx = blockIdx.x * blockDim.x + threadIdx.x;
    if (idx >= total) return;
    int c = idx & 511;
    int n = idx >> 9;
    const uint8_t* p = in + (size_t)n * 4 * 512 + sigma_ch(c);
    uint8_t v0 = p[0], v1 = p[512], v2 = p[1024], v3 = p[1536];
    uint8_t v = v0 > v1 ? v0 : v1;
    uint8_t w = v2 > v3 ? v2 : v3;
    uint8_t m = v > w ? v : w;
    float sc = __fdiv_rn(15.0f, __ldg(&alphas[12]));
    out[idx] = __fdiv_rn((float)m, sc);
}

// ----------------------------------------------------------------------------
// FC: 64x64 tile, 4x4 per thread (sequential k order -> bitwise-identical)
// ----------------------------------------------------------------------------
__global__ __launch_bounds__(256) void fc64_kernel(
    const float* __restrict__ act, const float* __restrict__ w,
    const float* __restrict__ bias, float* __restrict__ out,
    int M, int N, int K, int dorelu)
{
    __shared__ float As[16][68];
    __shared__ float Ws[16][68];
    const int t  = threadIdx.x;
    const int tx = t & 15, ty = t >> 4;
    const int mb = blockIdx.y * 64, nb = blockIdx.x * 64;

    float acc[4][4];
    #pragma unroll
    for (int i = 0; i < 4; i++)
        #pragma unroll
        for (int j = 0; j < 4; j++) acc[i][j] = 0.f;

    for (int kt = 0; kt < K; kt += 16) {
        #pragma unroll
        for (int u = 0; u < 4; u++) {
            int idx = t * 4 + u;
            int mm = idx >> 4, kk = idx & 15;
            As[kk][mm] = (mb + mm < M) ? act[(size_t)(mb + mm) * K + kt + kk] : 0.f;
            Ws[kk][mm] = (nb + mm < N) ? w[(size_t)(nb + mm) * K + kt + kk] : 0.f;
        }
        __syncthreads();
        #pragma unroll
        for (int kk = 0; kk < 16; kk++) {
            float av[4], bv[4];
            #pragma unroll
            for (int i = 0; i < 4; i++) av[i] = As[kk][ty * 4 + i];
            #pragma unroll
            for (int j = 0; j < 4; j++) bv[j] = Ws[kk][tx * 4 + j];
            #pragma unroll
            for (int i = 0; i < 4; i++)
                #pragma unroll
                for (int j = 0; j < 4; j++)
                    acc[i][j] = fmaf(av[i], bv[j], acc[i][j]);
        }
        __syncthreads();
    }

    #pragma unroll
    for (int i = 0; i < 4; i++) {
        int row = mb + ty * 4 + i;
        if (row >= M) continue;
        #pragma unroll
        for (int j = 0; j < 4; j++) {
            int col = nb + tx * 4 + j;
            if (col >= N) continue;
            float v = acc[i][j] + bias[col];
            if (dorelu) v = fmaxf(v, 0.f);
            out[(size_t)row * N + col] = v;
        }
    }
}

// ----------------------------------------------------------------------------
// Host orchestration
// ----------------------------------------------------------------------------
struct LayerCfg { int cin, cout, h; bool pool_after; };
static const LayerCfg g_layers[NLAYERS] = {
    {  3,  64, 32, false},
    { 64,  64, 32, true },
    { 64, 128, 16, false},
    {128, 128, 16, true },
    {128, 256,  8, false},
    {256, 256,  8, false},
    {256, 256,  8, true },
    {256, 512,  4, false},
    {512, 512,  4, false},
    {512, 512,  4, true },
    {512, 512,  2, false},
    {512, 512,  2, false},
    {512, 512,  2, true },
};

static int ilog2i(int v) { int r = 0; while ((1 << r) < v) r++; return r; }

extern "C" void kernel_launch(void* const* d_in, const int* in_sizes, int n_in,
                              void* d_out, int out_size) {
    (void)in_sizes; (void)n_in; (void)out_size;

    const float* x      = (const float*)d_in[0];
    const float* convw[NLAYERS];
    for (int i = 0; i < NLAYERS; i++) convw[i] = (const float*)d_in[1 + i];
    const float* alphas = (const float*)d_in[14];
    const float* fc1_w  = (const float*)d_in[15];
    const float* fc1_b  = (const float*)d_in[16];
    const float* fc2_w  = (const float*)d_in[17];
    const float* fc2_b  = (const float*)d_in[18];
    const float* fc3_w  = (const float*)d_in[19];
    const float* fc3_b  = (const float*)d_in[20];

    uint8_t *a8A, *a8B;
    float *fc0, *fcA, *fcB, *wq0, *scale, *Ffp;
    int *wq8, *thr;
    double *partial;
    cudaGetSymbolAddress((void**)&a8A,     g_act8A);
    cudaGetSymbolAddress((void**)&a8B,     g_act8B);
    cudaGetSymbolAddress((void**)&fc0,     g_fc0);
    cudaGetSymbolAddress((void**)&fcA,     g_fcA);
    cudaGetSymbolAddress((void**)&fcB,     g_fcB);
    cudaGetSymbolAddress((void**)&wq0,     g_wq0);
    cudaGetSymbolAddress((void**)&wq8,     g_wq8);
    cudaGetSymbolAddress((void**)&partial, g_partial);
    cudaGetSymbolAddress((void**)&scale,   g_scale);
    cudaGetSymbolAddress((void**)&thr,     g_thr);
    cudaGetSymbolAddress((void**)&Ffp,     g_Ff);

    static bool attr_set = false;
    if (!attr_set) {
        cudaFuncSetAttribute(conv_frag_kernel<256, 2, 4>,
                             cudaFuncAttributeMaxDynamicSharedMemorySize, 96 * 1024);
        attr_set = true;
    }

    PackArgs pa;
    long acc_off = 0;
    int max_pack_blocks = 1;
    for (int i = 1; i < NLAYERS; i++) {
        int li = i - 1;
        int CIN = g_layers[i].cin, COUT = g_layers[i].cout;
        int COUTP = ((COUT + 127) / 128) * 128;
        int K4 = (CIN * 9) >> 2;
        int KT8 = K4 >> 3;
        int nwords = KT8 * (COUTP >> 4) * 128;
        pa.w[li]      = convw[i];
        pa.off[li]    = acc_off;
        pa.cin[li]    = CIN;
        pa.cout[li]   = COUT;
        pa.coutp[li]  = COUTP;
        pa.sh[li]     = ilog2i(CIN >> 2);
        pa.nwords[li] = nwords;
        acc_off += nwords;
        int blks = (nwords + 255) / 256;
        if (blks > max_pack_blocks) max_pack_blocks = blks;
    }

    AbsArgs aa;
    for (int i = 0; i < NLAYERS; i++) {
        aa.p[i] = convw[i];
        aa.n[i] = g_layers[i].cout * g_layers[i].cin * 9;
    }

    absum_all_kernel<<<dim3(256, 13), 256>>>(aa, partial);
    finalize_all_kernel<<<13, 256>>>(aa, partial, scale);
    thr_kernel<<<12, 17>>>(alphas, scale, thr, Ffp);
    quantw0_kernel<<<(27 * 64 + 255) / 256, 256>>>(convw[0], 27 * 64, 27, 64, scale, wq0);
    pack_frag_kernel<<<dim3(max_pack_blocks, 12), 256>>>(pa, scale, wq8);

    {
        int N = BATCH * 32 * 32;
        conv0_kernel<<<dim3(N / 256, 1), 256>>>(x, wq0, a8A, alphas, scale);
    }

    uint8_t* buf[2] = {a8A, a8B};
    int cur = 0;

    for (int i = 1; i < NLAYERS; i++) {
        const LayerCfg& L = g_layers[i];
        int li = i - 1;
        int N = BATCH * L.h * L.h;
        int dst = 1 - cur;
        int sh = pa.sh[li];
        int COUTP = pa.coutp[li];
        int gy = COUTP / 128;
        int hwsh = ilog2i(L.h * L.h);
        int wsh  = ilog2i(L.h);

        if (N >= 256 && (N / 256) * gy >= 148) {
            size_t smem = 2 * 2048 * 4 + 2 * 256 * 24 * 4;   // 65536
            dim3 grid(N / 256, gy);
            conv_frag_kernel<256, 2, 4><<<grid, 256, smem>>>(
                buf[cur], wq8 + pa.off[li], buf[dst],
                L.cin, L.cout, L.h, sh, COUTP, hwsh, wsh, thr, Ffp, i);
        } else if (N >= 128 && (N / 128) * gy >= 148) {
            size_t smem = 2 * 2048 * 4 + 2 * 128 * 24 * 4;   // 40960
            dim3 grid(N / 128, gy);
            conv_frag_kernel<128, 2, 4><<<grid, 256, smem>>>(
                buf[cur], wq8 + pa.off[li], buf[dst],
                L.cin, L.cout, L.h, sh, COUTP, hwsh, wsh, thr, Ffp, i);
        } else {
            size_t smem = 2 * 2048 * 4 + 2 * 64 * 24 * 4;    // 28672
            dim3 grid(N / 64, gy);
            conv_frag_kernel<64, 4, 2><<<grid, 256, smem>>>(
                buf[cur], wq8 + pa.off[li], buf[dst],
                L.cin, L.cout, L.h, sh, COUTP, hwsh, wsh, thr, Ffp, i);
        }
        cur = dst;
        if (L.pool_after) {
            if (i == NLAYERS - 1) {
                pool_final_kernel<<<(BATCH * 512 + 255) / 256, 256>>>(buf[cur], fc0, alphas);
            } else {
                int dst2 = 1 - cur;
                int Hout = L.h >> 1;
                int total = BATCH * Hout * Hout * L.cout;
                pool8_kernel<<<(total + 255) / 256, 256>>>(buf[cur], buf[dst2], L.cout, L.h);
                cur = dst2;
            }
        }
    }

    {
        dim3 grid1(512 / 64, BATCH / 64);
        fc64_kernel<<<grid1, 256>>>(fc0, fc1_w, fc1_b, fcA, BATCH, 512, 512, 1);
        fc64_kernel<<<grid1, 256>>>(fcA, fc2_w, fc2_b, fcB, BATCH, 512, 512, 1);
        dim3 grid3(1, BATCH / 64);
        fc64_kernel<<<grid3, 256>>>(fcB, fc3_w, fc3_b, (float*)d_out, BATCH, 10, 512, 0);
    }
}

// round 15
// speedup vs baseline: 1.0727x; 1.0727x over previous
#include <cuda_runtime.h>
#include <cstdint>

// ============================================================================
// Quantized VGG forward (batch 512) — integer levels end-to-end.
// Convs 1-12: IMMA m16n8k32 (s8 x u8 -> s32, exact), fragment-ordered weights,
// K-chunk 64, LDS.64 B fragments (channel-interleaved storage), fp64-factor
// quant epilogue (verified bit-exact) with SMEM-staged COALESCED stores.
// ============================================================================

#define BATCH 512
#define NLAYERS 13

#define ACT8_ELEMS (512*64*32*32)
#define WQ8_WORDS  4000000

__device__ __align__(256) uint8_t g_act8A[ACT8_ELEMS];
__device__ __align__(256) uint8_t g_act8B[ACT8_ELEMS];
__device__ float   g_fc0[BATCH * 512];
__device__ float   g_fcA[BATCH * 512];
__device__ float   g_fcB[BATCH * 512];
__device__ float   g_wq0[32 * 64];
__device__ __align__(256) int g_wq8[WQ8_WORDS];
__device__ double  g_partial[NLAYERS * 256];
__device__ float   g_scale[NLAYERS * 2];

struct AbsArgs  { const float* p[13]; int n[13]; };
struct PackArgs { const float* w[12]; long off[12]; int cin[12]; int cout[12];
                  int coutp[12]; int sh[12]; int nwords[12]; };

// Channel permutation: within each 32-channel group, logical word lw stored at
// position s(lw) = ((lw&3)<<1)|(lw>>2). Preserves (c&3), so 4-aligned groups of
// 4 consecutive bytes stay contiguous.
__device__ __forceinline__ int sigma_ch(int c) {
    int lw = (c >> 2) & 7;
    int s  = ((lw & 3) << 1) | (lw >> 2);
    return (c & ~31) + s * 4 + (c & 3);
}

// ----------------------------------------------------------------------------
// asm helpers
// ----------------------------------------------------------------------------
__device__ __forceinline__ void cp16(uint32_t saddr, const void* g, unsigned sz) {
    asm volatile("cp.async.cg.shared.global [%0], [%1], 16, %2;"
                 :: "r"(saddr), "l"(g), "r"(sz) : "memory");
}
__device__ __forceinline__ void cp_commit() {
    asm volatile("cp.async.commit_group;" ::: "memory");
}
__device__ __forceinline__ void cp_wait0() {
    asm volatile("cp.async.wait_group 0;" ::: "memory");
}
__device__ __forceinline__ void imma16832(int* c, const int* a, const unsigned* b) {
    asm volatile(
        "mma.sync.aligned.m16n8k32.row.col.s32.s8.u8.s32 "
        "{%0,%1,%2,%3}, {%4,%5,%6,%7}, {%8,%9}, {%0,%1,%2,%3};"
        : "+r"(c[0]), "+r"(c[1]), "+r"(c[2]), "+r"(c[3])
        : "r"(a[0]), "r"(a[1]), "r"(a[2]), "r"(a[3]),
          "r"(b[0]), "r"(b[1]));
}

// ----------------------------------------------------------------------------
// Fused prep (identical reduction order -> same scale bits as R6-R14)
// ----------------------------------------------------------------------------
__global__ void absum_all_kernel(AbsArgs aa, double* __restrict__ partial) {
    int layer = blockIdx.y;
    const float* w = aa.p[layer];
    int n = aa.n[layer];
    __shared__ double s[256];
    double acc = 0.0;
    for (int i = blockIdx.x * 256 + threadIdx.x; i < n; i += 256 * 256)
        acc += (double)fabsf(w[i]);
    s[threadIdx.x] = acc;
    __syncthreads();
    for (int o = 128; o > 0; o >>= 1) {
        if (threadIdx.x < o) s[threadIdx.x] += s[threadIdx.x + o];
        __syncthreads();
    }
    if (threadIdx.x == 0) partial[layer * 256 + blockIdx.x] = s[0];
}

__global__ void finalize_all_kernel(AbsArgs aa, const double* __restrict__ partial,
                                    float* __restrict__ scale_out) {
    int layer = blockIdx.x;
    __shared__ double s[256];
    s[threadIdx.x] = partial[layer * 256 + threadIdx.x];
    __syncthreads();
    for (int o = 128; o > 0; o >>= 1) {
        if (threadIdx.x < o) s[threadIdx.x] += s[threadIdx.x + o];
        __syncthreads();
    }
    if (threadIdx.x == 0) {
        float sum_f = (float)s[0];
        float mean  = __fdiv_rn(sum_f, (float)aa.n[layer]);
        float alpha = 2.0f * mean;
        float sw    = __fdiv_rn(7.0f, alpha);
        scale_out[layer * 2 + 0] = alpha;
        scale_out[layer * 2 + 1] = sw;
    }
}

__global__ void quantw0_kernel(const float* __restrict__ w, int n, int K, int Cout,
                               const float* __restrict__ scale_p, float* __restrict__ wq_t) {
    int idx = blockIdx.x * blockDim.x + threadIdx.x;
    if (idx >= n) return;
    float alpha = scale_p[0];
    float s     = scale_p[1];
    float wc = fminf(fmaxf(w[idx], -alpha), alpha);
    float m  = rintf(wc * s);
    int mo = idx / K;
    int k  = idx - mo * K;
    wq_t[k * Cout + mo] = m;
}

// Fragment-ordered pack, LOGICAL k4 mapping (R13-verified).
__global__ void pack_frag_kernel(PackArgs pa, const float* __restrict__ scale,
                                 int* __restrict__ wq8) {
    int layer = blockIdx.y;
    int nw = pa.nwords[layer];
    int idx = blockIdx.x * 256 + threadIdx.x;
    if (idx >= nw) return;
    int q    = idx & 3;
    int lane = (idx >> 2) & 31;
    int blk  = idx >> 7;
    int nrb  = pa.coutp[layer] >> 4;
    int kt   = blk / nrb;
    int rblk = blk - kt * nrb;
    int gid = lane >> 2, tig = lane & 3;
    int row = rblk * 16 + ((q & 1) << 3) + gid;
    int k4  = kt * 8 + ((q >> 1) << 2) + tig;       // logical channel-word
    int val = 0;
    int COUT = pa.cout[layer];
    if (row < COUT) {
        int CIN = pa.cin[layer];
        int sh = pa.sh[layer];
        int cmask = (1 << sh) - 1;
        int rs = k4 >> sh;
        int ci0 = (k4 & cmask) << 2;                // logical channel base
        int r = rs / 3, s2 = rs - r * 3;
        float alpha = scale[(layer + 1) * 2 + 0];
        float s     = scale[(layer + 1) * 2 + 1];
        const float* w = pa.w[layer];
        unsigned pack = 0;
        #pragma unroll
        for (int t = 0; t < 4; t++) {
            int ci = ci0 + t;
            float v = w[((row * CIN + ci) * 3 + r) * 3 + s2];
            float wc = fminf(fmaxf(v, -alpha), alpha);
            int mi = (int)rintf(wc * s);
            pack |= ((unsigned)(mi & 0xFF)) << (8 * t);
        }
        val = (int)pack;
    }
    wq8[pa.off[layer] + idx] = val;
}

// ----------------------------------------------------------------------------
// Layer 0 conv: fp32 GEMM (K=27), tile 64x256; fp64 epilogue.
// ----------------------------------------------------------------------------
__global__ __launch_bounds__(256) void conv0_kernel(
    const float* __restrict__ x, const float* __restrict__ wq_t,
    uint8_t* __restrict__ out,
    const float* __restrict__ alphas, const float* __restrict__ scale_p)
{
    const int CIN = 3, COUT = 64, H = 32, W = 32, HW = 1024;
    const int K = 27;

    __shared__ float As[8][64];
    __shared__ float Bs[8][256];

    const int t = threadIdx.x;
    const int bx = blockIdx.x;

    const int jcol0 = bx * 256 + t;
    const int n0 = jcol0 >> 10;
    const int rem0 = jcol0 & 1023;
    const int y0 = rem0 >> 5;
    const int x0 = rem0 & 31;
    const float* inbase = x + (size_t)n0 * CIN * HW;

    float acc[8][8];
    #pragma unroll
    for (int i = 0; i < 8; i++)
        #pragma unroll
        for (int j = 0; j < 8; j++) acc[i][j] = 0.f;

    const int tm0 = (t & 7) * 8;
    const int tn0 = (t >> 3) * 8;

    for (int kt = 0; kt < 4; ++kt) {
        const int kbase = kt * 8;
        #pragma unroll
        for (int u = 0; u < 2; u++) {
            int idx = t * 2 + u;
            int col = idx & 63;
            int kk  = idx >> 6;
            int kg = kbase + kk;
            As[kk][col] = (kg < K) ? wq_t[kg * COUT + col] : 0.f;
        }
        #pragma unroll
        for (int u = 0; u < 8; u++) {
            int kg = kbase + u;
            float v = 0.f;
            if (kg < K) {
                int ci = kg / 9;
                int rs = kg - ci * 9;
                int r = rs / 3;
                int s2 = rs - r * 3;
                int yy = y0 + r - 1;
                int xx = x0 + s2 - 1;
                if (yy >= 0 && yy < H && xx >= 0 && xx < W)
                    v = inbase[ci * HW + yy * W + xx];
            }
            Bs[u][t] = v;
        }
        __syncthreads();
        #pragma unroll
        for (int kk = 0; kk < 8; kk++) {
            float a[8], b[8];
            #pragma unroll
            for (int i = 0; i < 8; i++) a[i] = As[kk][tm0 + i];
            #pragma unroll
            for (int j = 0; j < 8; j++) b[j] = Bs[kk][tn0 + j];
            #pragma unroll
            for (int i = 0; i < 8; i++)
                #pragma unroll
                for (int j = 0; j < 8; j++)
                    acc[i][j] = fmaf(a[i], b[j], acc[i][j]);
        }
        __syncthreads();
    }

    const float alpha_a = __ldg(&alphas[0]);
    const float s_w     = scale_p[1];
    const double F = (15.0 / (double)alpha_a) / (double)s_w;

    #pragma unroll
    for (int i = 0; i < 8; i++) {
        int m = tm0 + i;
        int ms = sigma_ch(m);
        #pragma unroll
        for (int j = 0; j < 8; j++) {
            int jj = bx * 256 + tn0 + j;
            int n2 = jj >> 10;
            int rm = jj & 1023;
            int yy = rm >> 5, xx = rm & 31;
            double td = (double)acc[i][j] * F;
            float tq = (float)rint(td);
            tq = fminf(fmaxf(tq, 0.f), 15.f);
            out[(((size_t)n2 * H + yy) * W + xx) * COUT + ms] = (uint8_t)tq;
        }
    }
}

// ----------------------------------------------------------------------------
// IMMA conv, K-chunk 16 packed words, LDS.64 B fragments; fp64 quant epilogue
// with SMEM-staged coalesced output stores.
// ----------------------------------------------------------------------------
template<int NBLK, int WM, int WN>
__global__ __launch_bounds__(256) void conv_frag_kernel(
    const uint8_t* __restrict__ in, const int* __restrict__ wfrag,
    uint8_t* __restrict__ out, int CIN, int COUT, int H, int sh, int COUTP,
    int hwsh, int wsh,
    const float* __restrict__ alphas, const float* __restrict__ scale_p, int layer)
{
    constexpr int WROWS = 128 / WM;
    constexpr int AM = WROWS / 16;
    constexpr int NW = NBLK / WN;
    constexpr int AN = NW / 8;
    constexpr int TPP = 256 / NBLK;
    constexpr int QPT = 4 / TPP;
    constexpr int ASTAGE = 2048;
    constexpr int BSTRIDE = 24;
    constexpr int SSTR = 144;           // staging row stride (bytes), mult of 16
    constexpr int CHUNKS = NBLK * 8 / 256;   // 16B write chunks per thread

    const int W = H, HW = H * H;
    const int hwmask = HW - 1, wmask = W - 1;
    const int K4 = (CIN * 9) >> 2;
    const int KT = K4 >> 4;
    const int cmask = (1 << sh) - 1;
    const int nrb = COUTP >> 4;

    extern __shared__ char smem[];
    int*      Asm = (int*)smem;
    unsigned* Bsm = (unsigned*)(smem + 2 * ASTAGE * 4);

    const int t = threadIdx.x;
    const int bx = blockIdx.x, by = blockIdx.y;
    const int lane = t & 31;
    const int wid  = t >> 5;
    const int gid  = lane >> 2;
    const int tig  = lane & 3;
    const int warp_m = wid / WN;
    const int warp_n = wid - warp_m * WN;

    const int p  = t % NBLK;
    const int qb = (t / NBLK) * QPT;
    int bn, byy, bxx;
    {
        int jcol = bx * NBLK + p;
        bn  = jcol >> hwsh;
        int rem = jcol & hwmask;
        byy = rem >> wsh;
        bxx = rem & wmask;
    }
    const int arblk = t >> 5;
    const int aoff  = (t & 31) * 4;

    uint32_t sAb = (uint32_t)__cvta_generic_to_shared(Asm);
    uint32_t sBb = (uint32_t)__cvta_generic_to_shared(Bsm);

    int c[AM][AN][4];
    #pragma unroll
    for (int am = 0; am < AM; am++)
        #pragma unroll
        for (int an = 0; an < AN; an++)
            #pragma unroll
            for (int q = 0; q < 4; q++) c[am][an][q] = 0;

    auto load_stage = [&](int kt2, int buf) {
        #pragma unroll
        for (int h = 0; h < 2; h++) {
            const int* ga = wfrag + ((long)(kt2 * 2 + h) * nrb + by * 8 + arblk) * 128 + aoff;
            cp16(sAb + (uint32_t)(buf * ASTAGE + h * 1024 + t * 4) * 4, ga, 16);
        }
        int kg0 = kt2 * 16;
        int rs = kg0 >> sh;
        int ci0 = (kg0 & cmask) << 2;
        int r = rs / 3, s2 = rs - r * 3;
        int yy = byy + r - 1;
        int xx = bxx + s2 - 1;
        bool ok = (yy >= 0 && yy < H && xx >= 0 && xx < W);
        const uint8_t* gb = ok ? in + ((size_t)bn * HW + (size_t)yy * W + xx) * CIN + ci0
                               : in;
        #pragma unroll
        for (int j = 0; j < QPT; j++) {
            int q = qb + j;
            cp16(sBb + (uint32_t)(buf * NBLK * BSTRIDE + p * BSTRIDE + q * 4) * 4,
                 gb + q * 16, ok ? 16u : 0u);
        }
        cp_commit();
    };

    load_stage(0, 0);

    for (int kt2 = 0; kt2 < KT; ++kt2) {
        const int buf = kt2 & 1;
        cp_wait0();
        __syncthreads();
        if (kt2 + 1 < KT) load_stage(kt2 + 1, buf ^ 1);

        const int*      Ab = Asm + buf * ASTAGE;
        const unsigned* Bb = Bsm + buf * NBLK * BSTRIDE;

        #pragma unroll
        for (int h = 0; h < 2; h++) {
            int a[AM][4];
            #pragma unroll
            for (int am = 0; am < AM; am++) {
                const int4 v = *reinterpret_cast<const int4*>(
                    &Ab[h * 1024 + (warp_m * AM + am) * 128 + lane * 4]);
                a[am][0] = v.x; a[am][1] = v.y; a[am][2] = v.z; a[am][3] = v.w;
            }
            unsigned b[AN][2];
            #pragma unroll
            for (int an = 0; an < AN; an++) {
                int pix = warp_n * NW + an * 8 + gid;
                const uint2 v = *reinterpret_cast<const uint2*>(
                    &Bb[pix * BSTRIDE + h * 8 + 2 * tig]);
                b[an][0] = v.x;
                b[an][1] = v.y;
            }
            #pragma unroll
            for (int am = 0; am < AM; am++)
                #pragma unroll
                for (int an = 0; an < AN; an++)
                    imma16832(c[am][an], a[am], b[an]);
        }
        __syncthreads();
    }

    // ---- Epilogue: fp64 quant (verified exact) + SMEM-staged coalesced store
    const float alpha_a = __ldg(&alphas[layer]);
    const float s_w     = scale_p[2 * layer + 1];
    const float alpha_p = __ldg(&alphas[layer - 1]);
    const double F = (15.0 / (double)alpha_a) / ((double)s_w * (15.0 / (double)alpha_p));

    uint8_t* stg = reinterpret_cast<uint8_t*>(Bsm);   // reuse B region (safe post-sync)

    // Precompute sigma of this thread's local rows (AM x 2)
    int srl[AM][2];
    const int rl0 = warp_m * WROWS + gid;
    #pragma unroll
    for (int am = 0; am < AM; am++) {
        srl[am][0] = sigma_ch(rl0 + am * 16);
        srl[am][1] = sigma_ch(rl0 + am * 16 + 8);
    }

    #pragma unroll
    for (int am = 0; am < AM; am++) {
        #pragma unroll
        for (int an = 0; an < AN; an++) {
            int pixl = warp_n * NW + an * 8 + 2 * tig;
            #pragma unroll
            for (int q = 0; q < 4; q++) {
                double td = (double)c[am][an][q] * F;
                float tq = (float)rint(td);
                tq = fminf(fmaxf(tq, 0.f), 15.f);
                stg[(pixl + (q & 1)) * SSTR + srl[am][q >> 1]] = (uint8_t)tq;
            }
        }
    }
    __syncthreads();

    // Coalesced writeout: 16 consecutive channels per STG.128
    const int remc = min(128, COUT - by * 128);
    const int nseg = remc >> 4;
    #pragma unroll
    for (int v = 0; v < CHUNKS; v++) {
        int idx = t + v * 256;
        int pix = idx >> 3;
        int seg = idx & 7;
        if (seg < nseg) {
            int4 val = *reinterpret_cast<const int4*>(stg + pix * SSTR + seg * 16);
            int col = bx * NBLK + pix;
            int n2 = col >> hwsh;
            int rm = col & hwmask;
            int yy = rm >> wsh, xx = rm & wmask;
            *reinterpret_cast<int4*>(
                out + (((size_t)n2 * H + yy) * W + xx) * COUT + by * 128 + seg * 16) = val;
        }
    }
}

// ----------------------------------------------------------------------------
// Pools
// ----------------------------------------------------------------------------
__global__ void pool8_kernel(const uint8_t* __restrict__ in, uint8_t* __restrict__ out,
                             int C, int Hin) {
    int Hout = Hin >> 1;
    int total = BATCH * Hout * Hout * C;
    int idx = blockIdx.x * blockDim.x + threadIdx.x;
    if (idx >= total) return;
    int c = idx % C;
    int tmp = idx / C;
    int x = tmp % Hout;
    tmp /= Hout;
    int y = tmp % Hout;
    int n = tmp / Hout;
    const uint8_t* p = in + (((size_t)n * Hin + 2 * y) * Hin + 2 * x) * C + c;
    size_t rows = (size_t)Hin * C;
    uint8_t v0 = p[0], v1 = p[C], v2 = p[rows], v3 = p[rows + C];
    uint8_t v = v0 > v1 ? v0 : v1;
    uint8_t w = v2 > v3 ? v2 : v3;
    out[idx] = v > w ? v : w;
}

__global__ void pool_final_kernel(const uint8_t* __restrict__ in, float* __restrict__ out,
                                  const float* __restrict__ alphas) {
    int total = BATCH * 512;
    int idx = blockIdx.x * blockDim.x + threadIdx.x;
    if (idx >= total) return;
    int c = idx & 511;
    int n = idx >> 9;
    const uint8_t* p = in + (size_t)n * 4 * 512 + sigma_ch(c);
    uint8_t v0 = p[0], v1 = p[512], v2 = p[1024], v3 = p[1536];
    uint8_t v = v0 > v1 ? v0 : v1;
    uint8_t w = v2 > v3 ? v2 : v3;
    uint8_t m = v > w ? v : w;
    float sc = __fdiv_rn(15.0f, __ldg(&alphas[12]));
    out[idx] = __fdiv_rn((float)m, sc);
}

// ----------------------------------------------------------------------------
// FC: 64x64 tile, 4x4 per thread (sequential k order -> bitwise-identical)
// ----------------------------------------------------------------------------
__global__ __launch_bounds__(256) void fc64_kernel(
    const float* __restrict__ act, const float* __restrict__ w,
    const float* __restrict__ bias, float* __restrict__ out,
    int M, int N, int K, int dorelu)
{
    __shared__ float As[16][68];
    __shared__ float Ws[16][68];
    const int t  = threadIdx.x;
    const int tx = t & 15, ty = t >> 4;
    const int mb = blockIdx.y * 64, nb = blockIdx.x * 64;

    float acc[4][4];
    #pragma unroll
    for (int i = 0; i < 4; i++)
        #pragma unroll
        for (int j = 0; j < 4; j++) acc[i][j] = 0.f;

    for (int kt = 0; kt < K; kt += 16) {
        #pragma unroll
        for (int u = 0; u < 4; u++) {
            int idx = t * 4 + u;
            int mm = idx >> 4, kk = idx & 15;
            As[kk][mm] = (mb + mm < M) ? act[(size_t)(mb + mm) * K + kt + kk] : 0.f;
            Ws[kk][mm] = (nb + mm < N) ? w[(size_t)(nb + mm) * K + kt + kk] : 0.f;
        }
        __syncthreads();
        #pragma unroll
        for (int kk = 0; kk < 16; kk++) {
            float av[4], bv[4];
            #pragma unroll
            for (int i = 0; i < 4; i++) av[i] = As[kk][ty * 4 + i];
            #pragma unroll
            for (int j = 0; j < 4; j++) bv[j] = Ws[kk][tx * 4 + j];
            #pragma unroll
            for (int i = 0; i < 4; i++)
                #pragma unroll
                for (int j = 0; j < 4; j++)
                    acc[i][j] = fmaf(av[i], bv[j], acc[i][j]);
        }
        __syncthreads();
    }

    #pragma unroll
    for (int i = 0; i < 4; i++) {
        int row = mb + ty * 4 + i;
        if (row >= M) continue;
        #pragma unroll
        for (int j = 0; j < 4; j++) {
            int col = nb + tx * 4 + j;
            if (col >= N) continue;
            float v = acc[i][j] + bias[col];
            if (dorelu) v = fmaxf(v, 0.f);
            out[(size_t)row * N + col] = v;
        }
    }
}

// ----------------------------------------------------------------------------
// Host orchestration
// ----------------------------------------------------------------------------
struct LayerCfg { int cin, cout, h; bool pool_after; };
static const LayerCfg g_layers[NLAYERS] = {
    {  3,  64, 32, false},
    { 64,  64, 32, true },
    { 64, 128, 16, false},
    {128, 128, 16, true },
    {128, 256,  8, false},
    {256, 256,  8, false},
    {256, 256,  8, true },
    {256, 512,  4, false},
    {512, 512,  4, false},
    {512, 512,  4, true },
    {512, 512,  2, false},
    {512, 512,  2, false},
    {512, 512,  2, true },
};

static int ilog2i(int v) { int r = 0; while ((1 << r) < v) r++; return r; }

extern "C" void kernel_launch(void* const* d_in, const int* in_sizes, int n_in,
                              void* d_out, int out_size) {
    (void)in_sizes; (void)n_in; (void)out_size;

    const float* x      = (const float*)d_in[0];
    const float* convw[NLAYERS];
    for (int i = 0; i < NLAYERS; i++) convw[i] = (const float*)d_in[1 + i];
    const float* alphas = (const float*)d_in[14];
    const float* fc1_w  = (const float*)d_in[15];
    const float* fc1_b  = (const float*)d_in[16];
    const float* fc2_w  = (const float*)d_in[17];
    const float* fc2_b  = (const float*)d_in[18];
    const float* fc3_w  = (const float*)d_in[19];
    const float* fc3_b  = (const float*)d_in[20];

    uint8_t *a8A, *a8B;
    float *fc0, *fcA, *fcB, *wq0, *scale;
    int *wq8;
    double *partial;
    cudaGetSymbolAddress((void**)&a8A,     g_act8A);
    cudaGetSymbolAddress((void**)&a8B,     g_act8B);
    cudaGetSymbolAddress((void**)&fc0,     g_fc0);
    cudaGetSymbolAddress((void**)&fcA,     g_fcA);
    cudaGetSymbolAddress((void**)&fcB,     g_fcB);
    cudaGetSymbolAddress((void**)&wq0,     g_wq0);
    cudaGetSymbolAddress((void**)&wq8,     g_wq8);
    cudaGetSymbolAddress((void**)&partial, g_partial);
    cudaGetSymbolAddress((void**)&scale,   g_scale);

    static bool attr_set = false;
    if (!attr_set) {
        cudaFuncSetAttribute(conv_frag_kernel<256, 2, 4>,
                             cudaFuncAttributeMaxDynamicSharedMemorySize, 96 * 1024);
        attr_set = true;
    }

    PackArgs pa;
    long acc_off = 0;
    int max_pack_blocks = 1;
    for (int i = 1; i < NLAYERS; i++) {
        int li = i - 1;
        int CIN = g_layers[i].cin, COUT = g_layers[i].cout;
        int COUTP = ((COUT + 127) / 128) * 128;
        int K4 = (CIN * 9) >> 2;
        int KT8 = K4 >> 3;
        int nwords = KT8 * (COUTP >> 4) * 128;
        pa.w[li]      = convw[i];
        pa.off[li]    = acc_off;
        pa.cin[li]    = CIN;
        pa.cout[li]   = COUT;
        pa.coutp[li]  = COUTP;
        pa.sh[li]     = ilog2i(CIN >> 2);
        pa.nwords[li] = nwords;
        acc_off += nwords;
        int blks = (nwords + 255) / 256;
        if (blks > max_pack_blocks) max_pack_blocks = blks;
    }

    AbsArgs aa;
    for (int i = 0; i < NLAYERS; i++) {
        aa.p[i] = convw[i];
        aa.n[i] = g_layers[i].cout * g_layers[i].cin * 9;
    }

    absum_all_kernel<<<dim3(256, 13), 256>>>(aa, partial);
    finalize_all_kernel<<<13, 256>>>(aa, partial, scale);
    quantw0_kernel<<<(27 * 64 + 255) / 256, 256>>>(convw[0], 27 * 64, 27, 64, scale, wq0);
    pack_frag_kernel<<<dim3(max_pack_blocks, 12), 256>>>(pa, scale, wq8);

    {
        int N = BATCH * 32 * 32;
        conv0_kernel<<<dim3(N / 256, 1), 256>>>(x, wq0, a8A, alphas, scale);
    }

    uint8_t* buf[2] = {a8A, a8B};
    int cur = 0;

    for (int i = 1; i < NLAYERS; i++) {
        const LayerCfg& L = g_layers[i];
        int li = i - 1;
        int N = BATCH * L.h * L.h;
        int dst = 1 - cur;
        int sh = pa.sh[li];
        int COUTP = pa.coutp[li];
        int gy = COUTP / 128;
        int hwsh = ilog2i(L.h * L.h);
        int wsh  = ilog2i(L.h);

        if (N >= 256 && (N / 256) * gy >= 148) {
            size_t smem = 2 * 2048 * 4 + 2 * 256 * 24 * 4;   // 65536
            dim3 grid(N / 256, gy);
            conv_frag_kernel<256, 2, 4><<<grid, 256, smem>>>(
                buf[cur], wq8 + pa.off[li], buf[dst],
                L.cin, L.cout, L.h, sh, COUTP, hwsh, wsh, alphas, scale, i);
        } else if (N >= 128 && (N / 128) * gy >= 148) {
            size_t smem = 2 * 2048 * 4 + 2 * 128 * 24 * 4;   // 40960
            dim3 grid(N / 128, gy);
            conv_frag_kernel<128, 2, 4><<<grid, 256, smem>>>(
                buf[cur], wq8 + pa.off[li], buf[dst],
                L.cin, L.cout, L.h, sh, COUTP, hwsh, wsh, alphas, scale, i);
        } else {
            size_t smem = 2 * 2048 * 4 + 2 * 64 * 24 * 4;    // 28672
            dim3 grid(N / 64, gy);
            conv_frag_kernel<64, 4, 2><<<grid, 256, smem>>>(
                buf[cur], wq8 + pa.off[li], buf[dst],
                L.cin, L.cout, L.h, sh, COUTP, hwsh, wsh, alphas, scale, i);
        }
        cur = dst;
        if (L.pool_after) {
            if (i == NLAYERS - 1) {
                pool_final_kernel<<<(BATCH * 512 + 255) / 256, 256>>>(buf[cur], fc0, alphas);
            } else {
                int dst2 = 1 - cur;
                int Hout = L.h >> 1;
                int total = BATCH * Hout * Hout * L.cout;
                pool8_kernel<<<(total + 255) / 256, 256>>>(buf[cur], buf[dst2], L.cout, L.h);
                cur = dst2;
            }
        }
    }

    {
        dim3 grid1(512 / 64, BATCH / 64);
        fc64_kernel<<<grid1, 256>>>(fc0, fc1_w, fc1_b, fcA, BATCH, 512, 512, 1);
        fc64_kernel<<<grid1, 256>>>(fcA, fc2_w, fc2_b, fcB, BATCH, 512, 512, 1);
        dim3 grid3(1, BATCH / 64);
        fc64_kernel<<<grid3, 256>>>(fcB, fc3_w, fc3_b, (float*)d_out, BATCH, 10, 512, 0);
    }
}

// round 17
// speedup vs baseline: 1.1261x; 1.0498x over previous
#include <cuda_runtime.h>
#include <cstdint>

// ============================================================================
// Quantized VGG forward (batch 512) — integer levels end-to-end.
// Convs 1-12: IMMA m16n8k32 (s8 x u8 -> s32, exact), fragment-ordered weights,
// K-chunk 64, LDS.64 B fragments, fp64-factor quant epilogue with SMEM-staged
// coalesced stores. MROWS-templated tile: layer 1 (COUT=64) runs a 64-row tile
// (no zero-padded mma work).
// (Resubmission of R16 — infra failure, kernel never executed.)
// ============================================================================

#define BATCH 512
#define NLAYERS 13

#define ACT8_ELEMS (512*64*32*32)
#define WQ8_WORDS  4000000

__device__ __align__(256) uint8_t g_act8A[ACT8_ELEMS];
__device__ __align__(256) uint8_t g_act8B[ACT8_ELEMS];
__device__ float   g_fc0[BATCH * 512];
__device__ float   g_fcA[BATCH * 512];
__device__ float   g_fcB[BATCH * 512];
__device__ float   g_wq0[32 * 64];
__device__ __align__(256) int g_wq8[WQ8_WORDS];
__device__ double  g_partial[NLAYERS * 256];
__device__ float   g_scale[NLAYERS * 2];

struct AbsArgs  { const float* p[13]; int n[13]; };
struct PackArgs { const float* w[12]; long off[12]; int cin[12]; int cout[12];
                  int coutp[12]; int sh[12]; int nwords[12]; };

// Channel permutation: within each 32-channel group, logical word lw stored at
// position s(lw) = ((lw&3)<<1)|(lw>>2). Preserves (c&3).
__device__ __forceinline__ int sigma_ch(int c) {
    int lw = (c >> 2) & 7;
    int s  = ((lw & 3) << 1) | (lw >> 2);
    return (c & ~31) + s * 4 + (c & 3);
}

// ----------------------------------------------------------------------------
// asm helpers
// ----------------------------------------------------------------------------
__device__ __forceinline__ void cp16(uint32_t saddr, const void* g, unsigned sz) {
    asm volatile("cp.async.cg.shared.global [%0], [%1], 16, %2;"
                 :: "r"(saddr), "l"(g), "r"(sz) : "memory");
}
__device__ __forceinline__ void cp_commit() {
    asm volatile("cp.async.commit_group;" ::: "memory");
}
__device__ __forceinline__ void cp_wait0() {
    asm volatile("cp.async.wait_group 0;" ::: "memory");
}
__device__ __forceinline__ void imma16832(int* c, const int* a, const unsigned* b) {
    asm volatile(
        "mma.sync.aligned.m16n8k32.row.col.s32.s8.u8.s32 "
        "{%0,%1,%2,%3}, {%4,%5,%6,%7}, {%8,%9}, {%0,%1,%2,%3};"
        : "+r"(c[0]), "+r"(c[1]), "+r"(c[2]), "+r"(c[3])
        : "r"(a[0]), "r"(a[1]), "r"(a[2]), "r"(a[3]),
          "r"(b[0]), "r"(b[1]));
}

// ----------------------------------------------------------------------------
// Fused prep (identical reduction order -> same scale bits as R6-R15)
// ----------------------------------------------------------------------------
__global__ void absum_all_kernel(AbsArgs aa, double* __restrict__ partial) {
    int layer = blockIdx.y;
    const float* w = aa.p[layer];
    int n = aa.n[layer];
    __shared__ double s[256];
    double acc = 0.0;
    for (int i = blockIdx.x * 256 + threadIdx.x; i < n; i += 256 * 256)
        acc += (double)fabsf(w[i]);
    s[threadIdx.x] = acc;
    __syncthreads();
    for (int o = 128; o > 0; o >>= 1) {
        if (threadIdx.x < o) s[threadIdx.x] += s[threadIdx.x + o];
        __syncthreads();
    }
    if (threadIdx.x == 0) partial[layer * 256 + blockIdx.x] = s[0];
}

__global__ void finalize_all_kernel(AbsArgs aa, const double* __restrict__ partial,
                                    float* __restrict__ scale_out) {
    int layer = blockIdx.x;
    __shared__ double s[256];
    s[threadIdx.x] = partial[layer * 256 + threadIdx.x];
    __syncthreads();
    for (int o = 128; o > 0; o >>= 1) {
        if (threadIdx.x < o) s[threadIdx.x] += s[threadIdx.x + o];
        __syncthreads();
    }
    if (threadIdx.x == 0) {
        float sum_f = (float)s[0];
        float mean  = __fdiv_rn(sum_f, (float)aa.n[layer]);
        float alpha = 2.0f * mean;
        float sw    = __fdiv_rn(7.0f, alpha);
        scale_out[layer * 2 + 0] = alpha;
        scale_out[layer * 2 + 1] = sw;
    }
}

__global__ void quantw0_kernel(const float* __restrict__ w, int n, int K, int Cout,
                               const float* __restrict__ scale_p, float* __restrict__ wq_t) {
    int idx = blockIdx.x * blockDim.x + threadIdx.x;
    if (idx >= n) return;
    float alpha = scale_p[0];
    float s     = scale_p[1];
    float wc = fminf(fmaxf(w[idx], -alpha), alpha);
    float m  = rintf(wc * s);
    int mo = idx / K;
    int k  = idx - mo * K;
    wq_t[k * Cout + mo] = m;
}

// Fragment-ordered pack, LOGICAL k4 mapping. Layout [kt8][nrb=COUTP/16][128].
__global__ void pack_frag_kernel(PackArgs pa, const float* __restrict__ scale,
                                 int* __restrict__ wq8) {
    int layer = blockIdx.y;
    int nw = pa.nwords[layer];
    int idx = blockIdx.x * 256 + threadIdx.x;
    if (idx >= nw) return;
    int q    = idx & 3;
    int lane = (idx >> 2) & 31;
    int blk  = idx >> 7;
    int nrb  = pa.coutp[layer] >> 4;
    int kt   = blk / nrb;
    int rblk = blk - kt * nrb;
    int gid = lane >> 2, tig = lane & 3;
    int row = rblk * 16 + ((q & 1) << 3) + gid;
    int k4  = kt * 8 + ((q >> 1) << 2) + tig;       // logical channel-word
    int val = 0;
    int COUT = pa.cout[layer];
    if (row < COUT) {
        int CIN = pa.cin[layer];
        int sh = pa.sh[layer];
        int cmask = (1 << sh) - 1;
        int rs = k4 >> sh;
        int ci0 = (k4 & cmask) << 2;                // logical channel base
        int r = rs / 3, s2 = rs - r * 3;
        float alpha = scale[(layer + 1) * 2 + 0];
        float s     = scale[(layer + 1) * 2 + 1];
        const float* w = pa.w[layer];
        unsigned pack = 0;
        #pragma unroll
        for (int t = 0; t < 4; t++) {
            int ci = ci0 + t;
            float v = w[((row * CIN + ci) * 3 + r) * 3 + s2];
            float wc = fminf(fmaxf(v, -alpha), alpha);
            int mi = (int)rintf(wc * s);
            pack |= ((unsigned)(mi & 0xFF)) << (8 * t);
        }
        val = (int)pack;
    }
    wq8[pa.off[layer] + idx] = val;
}

// ----------------------------------------------------------------------------
// Layer 0 conv: fp32 GEMM (K=27), tile 64x256; fp64 epilogue.
// ----------------------------------------------------------------------------
__global__ __launch_bounds__(256) void conv0_kernel(
    const float* __restrict__ x, const float* __restrict__ wq_t,
    uint8_t* __restrict__ out,
    const float* __restrict__ alphas, const float* __restrict__ scale_p)
{
    const int CIN = 3, COUT = 64, H = 32, W = 32, HW = 1024;
    const int K = 27;

    __shared__ float As[8][64];
    __shared__ float Bs[8][256];

    const int t = threadIdx.x;
    const int bx = blockIdx.x;

    const int jcol0 = bx * 256 + t;
    const int n0 = jcol0 >> 10;
    const int rem0 = jcol0 & 1023;
    const int y0 = rem0 >> 5;
    const int x0 = rem0 & 31;
    const float* inbase = x + (size_t)n0 * CIN * HW;

    float acc[8][8];
    #pragma unroll
    for (int i = 0; i < 8; i++)
        #pragma unroll
        for (int j = 0; j < 8; j++) acc[i][j] = 0.f;

    const int tm0 = (t & 7) * 8;
    const int tn0 = (t >> 3) * 8;

    for (int kt = 0; kt < 4; ++kt) {
        const int kbase = kt * 8;
        #pragma unroll
        for (int u = 0; u < 2; u++) {
            int idx = t * 2 + u;
            int col = idx & 63;
            int kk  = idx >> 6;
            int kg = kbase + kk;
            As[kk][col] = (kg < K) ? wq_t[kg * COUT + col] : 0.f;
        }
        #pragma unroll
        for (int u = 0; u < 8; u++) {
            int kg = kbase + u;
            float v = 0.f;
            if (kg < K) {
                int ci = kg / 9;
                int rs = kg - ci * 9;
                int r = rs / 3;
                int s2 = rs - r * 3;
                int yy = y0 + r - 1;
                int xx = x0 + s2 - 1;
                if (yy >= 0 && yy < H && xx >= 0 && xx < W)
                    v = inbase[ci * HW + yy * W + xx];
            }
            Bs[u][t] = v;
        }
        __syncthreads();
        #pragma unroll
        for (int kk = 0; kk < 8; kk++) {
            float a[8], b[8];
            #pragma unroll
            for (int i = 0; i < 8; i++) a[i] = As[kk][tm0 + i];
            #pragma unroll
            for (int j = 0; j < 8; j++) b[j] = Bs[kk][tn0 + j];
            #pragma unroll
            for (int i = 0; i < 8; i++)
                #pragma unroll
                for (int j = 0; j < 8; j++)
                    acc[i][j] = fmaf(a[i], b[j], acc[i][j]);
        }
        __syncthreads();
    }

    const float alpha_a = __ldg(&alphas[0]);
    const float s_w     = scale_p[1];
    const double F = (15.0 / (double)alpha_a) / (double)s_w;

    #pragma unroll
    for (int i = 0; i < 8; i++) {
        int m = tm0 + i;
        int ms = sigma_ch(m);
        #pragma unroll
        for (int j = 0; j < 8; j++) {
            int jj = bx * 256 + tn0 + j;
            int n2 = jj >> 10;
            int rm = jj & 1023;
            int yy = rm >> 5, xx = rm & 31;
            double td = (double)acc[i][j] * F;
            float tq = (float)rint(td);
            tq = fminf(fmaxf(tq, 0.f), 15.f);
            out[(((size_t)n2 * H + yy) * W + xx) * COUT + ms] = (uint8_t)tq;
        }
    }
}

// ----------------------------------------------------------------------------
// IMMA conv, K-chunk 16 packed words, MROWS-templated (64 or 128 output rows).
// ----------------------------------------------------------------------------
template<int NBLK, int WM, int WN, int MROWS>
__global__ __launch_bounds__(256) void conv_frag_kernel(
    const uint8_t* __restrict__ in, const int* __restrict__ wfrag,
    uint8_t* __restrict__ out, int CIN, int COUT, int H, int sh, int COUTP,
    int hwsh, int wsh,
    const float* __restrict__ alphas, const float* __restrict__ scale_p, int layer)
{
    constexpr int WROWS = MROWS / WM;
    constexpr int AM = WROWS / 16;
    constexpr int NW = NBLK / WN;
    constexpr int AN = NW / 8;
    constexpr int TPP = 256 / NBLK;
    constexpr int QPT = 4 / TPP;
    constexpr int NRB = MROWS / 16;
    constexpr int ACH = NRB * 128;          // A words per kt8 block
    constexpr int ASTAGE = 2 * ACH;         // A words per buffer (2 kt8 blocks)
    constexpr int ALOADS = (2 * ACH) / (256 * 4);
    constexpr int BSTRIDE = 24;
    constexpr int SSTR = MROWS + 16;        // staging stride (bytes), mult of 16
    constexpr int SEGS = MROWS / 16;
    constexpr int CHUNKS = NBLK * SEGS / 256;

    const int W = H, HW = H * H;
    const int hwmask = HW - 1, wmask = W - 1;
    const int K4 = (CIN * 9) >> 2;
    const int KT = K4 >> 4;
    const int cmask = (1 << sh) - 1;
    const int nrb = COUTP >> 4;

    extern __shared__ char smem[];
    int*      Asm = (int*)smem;
    unsigned* Bsm = (unsigned*)(smem + 2 * ASTAGE * 4);

    const int t = threadIdx.x;
    const int bx = blockIdx.x, by = blockIdx.y;
    const int lane = t & 31;
    const int wid  = t >> 5;
    const int gid  = lane >> 2;
    const int tig  = lane & 3;
    const int warp_m = wid / WN;
    const int warp_n = wid - warp_m * WN;

    const int p  = t % NBLK;
    const int qb = (t / NBLK) * QPT;
    int bn, byy, bxx;
    {
        int jcol = bx * NBLK + p;
        bn  = jcol >> hwsh;
        int rem = jcol & hwmask;
        byy = rem >> wsh;
        bxx = rem & wmask;
    }

    uint32_t sAb = (uint32_t)__cvta_generic_to_shared(Asm);
    uint32_t sBb = (uint32_t)__cvta_generic_to_shared(Bsm);

    int c[AM][AN][4];
    #pragma unroll
    for (int am = 0; am < AM; am++)
        #pragma unroll
        for (int an = 0; an < AN; an++)
            #pragma unroll
            for (int q = 0; q < 4; q++) c[am][an][q] = 0;

    auto load_stage = [&](int kt2, int buf) {
        #pragma unroll
        for (int u = 0; u < ALOADS; u++) {
            int widx = u * 1024 + t * 4;
            int h    = widx / ACH;
            int rem2 = widx - h * ACH;
            int rblk = rem2 >> 7;
            int off  = rem2 & 127;
            const int* ga = wfrag + ((long)(kt2 * 2 + h) * nrb + by * NRB + rblk) * 128 + off;
            cp16(sAb + (uint32_t)(buf * ASTAGE + widx) * 4, ga, 16);
        }
        int kg0 = kt2 * 16;
        int rs = kg0 >> sh;
        int ci0 = (kg0 & cmask) << 2;
        int r = rs / 3, s2 = rs - r * 3;
        int yy = byy + r - 1;
        int xx = bxx + s2 - 1;
        bool ok = (yy >= 0 && yy < H && xx >= 0 && xx < W);
        const uint8_t* gb = ok ? in + ((size_t)bn * HW + (size_t)yy * W + xx) * CIN + ci0
                               : in;
        #pragma unroll
        for (int j = 0; j < QPT; j++) {
            int q = qb + j;
            cp16(sBb + (uint32_t)(buf * NBLK * BSTRIDE + p * BSTRIDE + q * 4) * 4,
                 gb + q * 16, ok ? 16u : 0u);
        }
        cp_commit();
    };

    load_stage(0, 0);

    for (int kt2 = 0; kt2 < KT; ++kt2) {
        const int buf = kt2 & 1;
        cp_wait0();
        __syncthreads();
        if (kt2 + 1 < KT) load_stage(kt2 + 1, buf ^ 1);

        const int*      Ab = Asm + buf * ASTAGE;
        const unsigned* Bb = Bsm + buf * NBLK * BSTRIDE;

        #pragma unroll
        for (int h = 0; h < 2; h++) {
            int a[AM][4];
            #pragma unroll
            for (int am = 0; am < AM; am++) {
                const int4 v = *reinterpret_cast<const int4*>(
                    &Ab[h * ACH + (warp_m * AM + am) * 128 + lane * 4]);
                a[am][0] = v.x; a[am][1] = v.y; a[am][2] = v.z; a[am][3] = v.w;
            }
            unsigned b[AN][2];
            #pragma unroll
            for (int an = 0; an < AN; an++) {
                int pix = warp_n * NW + an * 8 + gid;
                const uint2 v = *reinterpret_cast<const uint2*>(
                    &Bb[pix * BSTRIDE + h * 8 + 2 * tig]);
                b[an][0] = v.x;
                b[an][1] = v.y;
            }
            #pragma unroll
            for (int am = 0; am < AM; am++)
                #pragma unroll
                for (int an = 0; an < AN; an++)
                    imma16832(c[am][an], a[am], b[an]);
        }
        __syncthreads();
    }

    // ---- Epilogue: fp64 quant (verified exact) + SMEM-staged coalesced store
    const float alpha_a = __ldg(&alphas[layer]);
    const float s_w     = scale_p[2 * layer + 1];
    const float alpha_p = __ldg(&alphas[layer - 1]);
    const double F = (15.0 / (double)alpha_a) / ((double)s_w * (15.0 / (double)alpha_p));

    uint8_t* stg = reinterpret_cast<uint8_t*>(Bsm);   // reuse B region (post-sync)

    int srl[AM][2];
    const int rl0 = warp_m * WROWS + gid;
    #pragma unroll
    for (int am = 0; am < AM; am++) {
        srl[am][0] = sigma_ch(rl0 + am * 16);
        srl[am][1] = sigma_ch(rl0 + am * 16 + 8);
    }

    #pragma unroll
    for (int am = 0; am < AM; am++) {
        #pragma unroll
        for (int an = 0; an < AN; an++) {
            int pixl = warp_n * NW + an * 8 + 2 * tig;
            #pragma unroll
            for (int q = 0; q < 4; q++) {
                double td = (double)c[am][an][q] * F;
                float tq = (float)rint(td);
                tq = fminf(fmaxf(tq, 0.f), 15.f);
                stg[(pixl + (q & 1)) * SSTR + srl[am][q >> 1]] = (uint8_t)tq;
            }
        }
    }
    __syncthreads();

    // Coalesced writeout: 16 consecutive channels per STG.128
    const int remc = min(MROWS, COUT - by * MROWS);
    const int nseg = remc >> 4;
    #pragma unroll
    for (int v = 0; v < CHUNKS; v++) {
        int idx = t + v * 256;
        int pix = idx / SEGS;
        int seg = idx % SEGS;
        if (seg < nseg) {
            int4 val = *reinterpret_cast<const int4*>(stg + pix * SSTR + seg * 16);
            int col = bx * NBLK + pix;
            int n2 = col >> hwsh;
            int rm = col & hwmask;
            int yy = rm >> wsh, xx = rm & wmask;
            *reinterpret_cast<int4*>(
                out + (((size_t)n2 * H + yy) * W + xx) * COUT + by * MROWS + seg * 16) = val;
        }
    }
}

// ----------------------------------------------------------------------------
// Pools
// ----------------------------------------------------------------------------
__global__ void pool8_kernel(const uint8_t* __restrict__ in, uint8_t* __restrict__ out,
                             int C, int Hin) {
    int Hout = Hin >> 1;
    int total = BATCH * Hout * Hout * C;
    int idx = blockIdx.x * blockDim.x + threadIdx.x;
    if (idx >= total) return;
    int c = idx % C;
    int tmp = idx / C;
    int x = tmp % Hout;
    tmp /= Hout;
    int y = tmp % Hout;
    int n = tmp / Hout;
    const uint8_t* p = in + (((size_t)n * Hin + 2 * y) * Hin + 2 * x) * C + c;
    size_t rows = (size_t)Hin * C;
    uint8_t v0 = p[0], v1 = p[C], v2 = p[rows], v3 = p[rows + C];
    uint8_t v = v0 > v1 ? v0 : v1;
    uint8_t w = v2 > v3 ? v2 : v3;
    out[idx] = v > w ? v : w;
}

__global__ void pool_final_kernel(const uint8_t* __restrict__ in, float* __restrict__ out,
                                  const float* __restrict__ alphas) {
    int total = BATCH * 512;
    int idx = blockIdx.x * blockDim.x + threadIdx.x;
    if (idx >= total) return;
    int c = idx & 511;
    int n = idx >> 9;
    const uint8_t* p = in + (size_t)n * 4 * 512 + sigma_ch(c);
    uint8_t v0 = p[0], v1 = p[512], v2 = p[1024], v3 = p[1536];
    uint8_t v = v0 > v1 ? v0 : v1;
    uint8_t w = v2 > v3 ? v2 : v3;
    uint8_t m = v > w ? v : w;
    float sc = __fdiv_rn(15.0f, __ldg(&alphas[12]));
    out[idx] = __fdiv_rn((float)m, sc);
}

// ----------------------------------------------------------------------------
// FC: 64x64 tile, 4x4 per thread (sequential k order -> bitwise-identical)
// ----------------------------------------------------------------------------
__global__ __launch_bounds__(256) void fc64_kernel(
    const float* __restrict__ act, const float* __restrict__ w,
    const float* __restrict__ bias, float* __restrict__ out,
    int M, int N, int K, int dorelu)
{
    __shared__ float As[16][68];
    __shared__ float Ws[16][68];
    const int t  = threadIdx.x;
    const int tx = t & 15, ty = t >> 4;
    const int mb = blockIdx.y * 64, nb = blockIdx.x * 64;

    float acc[4][4];
    #pragma unroll
    for (int i = 0; i < 4; i++)
        #pragma unroll
        for (int j = 0; j < 4; j++) acc[i][j] = 0.f;

    for (int kt = 0; kt < K; kt += 16) {
        #pragma unroll
        for (int u = 0; u < 4; u++) {
            int idx = t * 4 + u;
            int mm = idx >> 4, kk = idx & 15;
            As[kk][mm] = (mb + mm < M) ? act[(size_t)(mb + mm) * K + kt + kk] : 0.f;
            Ws[kk][mm] = (nb + mm < N) ? w[(size_t)(nb + mm) * K + kt + kk] : 0.f;
        }
        __syncthreads();
        #pragma unroll
        for (int kk = 0; kk < 16; kk++) {
            float av[4], bv[4];
            #pragma unroll
            for (int i = 0; i < 4; i++) av[i] = As[kk][ty * 4 + i];
            #pragma unroll
            for (int j = 0; j < 4; j++) bv[j] = Ws[kk][tx * 4 + j];
            #pragma unroll
            for (int i = 0; i < 4; i++)
                #pragma unroll
                for (int j = 0; j < 4; j++)
                    acc[i][j] = fmaf(av[i], bv[j], acc[i][j]);
        }
        __syncthreads();
    }

    #pragma unroll
    for (int i = 0; i < 4; i++) {
        int row = mb + ty * 4 + i;
        if (row >= M) continue;
        #pragma unroll
        for (int j = 0; j < 4; j++) {
            int col = nb + tx * 4 + j;
            if (col >= N) continue;
            float v = acc[i][j] + bias[col];
            if (dorelu) v = fmaxf(v, 0.f);
            out[(size_t)row * N + col] = v;
        }
    }
}

// ----------------------------------------------------------------------------
// Host orchestration
// ----------------------------------------------------------------------------
struct LayerCfg { int cin, cout, h; bool pool_after; };
static const LayerCfg g_layers[NLAYERS] = {
    {  3,  64, 32, false},
    { 64,  64, 32, true },
    { 64, 128, 16, false},
    {128, 128, 16, true },
    {128, 256,  8, false},
    {256, 256,  8, false},
    {256, 256,  8, true },
    {256, 512,  4, false},
    {512, 512,  4, false},
    {512, 512,  4, true },
    {512, 512,  2, false},
    {512, 512,  2, false},
    {512, 512,  2, true },
};

static int ilog2i(int v) { int r = 0; while ((1 << r) < v) r++; return r; }

extern "C" void kernel_launch(void* const* d_in, const int* in_sizes, int n_in,
                              void* d_out, int out_size) {
    (void)in_sizes; (void)n_in; (void)out_size;

    const float* x      = (const float*)d_in[0];
    const float* convw[NLAYERS];
    for (int i = 0; i < NLAYERS; i++) convw[i] = (const float*)d_in[1 + i];
    const float* alphas = (const float*)d_in[14];
    const float* fc1_w  = (const float*)d_in[15];
    const float* fc1_b  = (const float*)d_in[16];
    const float* fc2_w  = (const float*)d_in[17];
    const float* fc2_b  = (const float*)d_in[18];
    const float* fc3_w  = (const float*)d_in[19];
    const float* fc3_b  = (const float*)d_in[20];

    uint8_t *a8A, *a8B;
    float *fc0, *fcA, *fcB, *wq0, *scale;
    int *wq8;
    double *partial;
    cudaGetSymbolAddress((void**)&a8A,     g_act8A);
    cudaGetSymbolAddress((void**)&a8B,     g_act8B);
    cudaGetSymbolAddress((void**)&fc0,     g_fc0);
    cudaGetSymbolAddress((void**)&fcA,     g_fcA);
    cudaGetSymbolAddress((void**)&fcB,     g_fcB);
    cudaGetSymbolAddress((void**)&wq0,     g_wq0);
    cudaGetSymbolAddress((void**)&wq8,     g_wq8);
    cudaGetSymbolAddress((void**)&partial, g_partial);
    cudaGetSymbolAddress((void**)&scale,   g_scale);

    static bool attr_set = false;
    if (!attr_set) {
        cudaFuncSetAttribute(conv_frag_kernel<256, 2, 4, 128>,
                             cudaFuncAttributeMaxDynamicSharedMemorySize, 96 * 1024);
        cudaFuncSetAttribute(conv_frag_kernel<256, 1, 8, 64>,
                             cudaFuncAttributeMaxDynamicSharedMemorySize, 96 * 1024);
        attr_set = true;
    }

    PackArgs pa;
    long acc_off = 0;
    int max_pack_blocks = 1;
    for (int i = 1; i < NLAYERS; i++) {
        int li = i - 1;
        int CIN = g_layers[i].cin, COUT = g_layers[i].cout;
        int MR = (i == 1) ? 64 : 128;                  // layer 1 uses 64-row tile
        int COUTP = ((COUT + MR - 1) / MR) * MR;
        int K4 = (CIN * 9) >> 2;
        int KT8 = K4 >> 3;
        int nwords = KT8 * (COUTP >> 4) * 128;
        pa.w[li]      = convw[i];
        pa.off[li]    = acc_off;
        pa.cin[li]    = CIN;
        pa.cout[li]   = COUT;
        pa.coutp[li]  = COUTP;
        pa.sh[li]     = ilog2i(CIN >> 2);
        pa.nwords[li] = nwords;
        acc_off += nwords;
        int blks = (nwords + 255) / 256;
        if (blks > max_pack_blocks) max_pack_blocks = blks;
    }

    AbsArgs aa;
    for (int i = 0; i < NLAYERS; i++) {
        aa.p[i] = convw[i];
        aa.n[i] = g_layers[i].cout * g_layers[i].cin * 9;
    }

    absum_all_kernel<<<dim3(256, 13), 256>>>(aa, partial);
    finalize_all_kernel<<<13, 256>>>(aa, partial, scale);
    quantw0_kernel<<<(27 * 64 + 255) / 256, 256>>>(convw[0], 27 * 64, 27, 64, scale, wq0);
    pack_frag_kernel<<<dim3(max_pack_blocks, 12), 256>>>(pa, scale, wq8);

    {
        int N = BATCH * 32 * 32;
        conv0_kernel<<<dim3(N / 256, 1), 256>>>(x, wq0, a8A, alphas, scale);
    }

    uint8_t* buf[2] = {a8A, a8B};
    int cur = 0;

    for (int i = 1; i < NLAYERS; i++) {
        const LayerCfg& L = g_layers[i];
        int li = i - 1;
        int N = BATCH * L.h * L.h;
        int dst = 1 - cur;
        int sh = pa.sh[li];
        int COUTP = pa.coutp[li];
        int hwsh = ilog2i(L.h * L.h);
        int wsh  = ilog2i(L.h);

        if (i == 1) {
            // 64-row tile: no zero-padded mma work (COUT=64)
            size_t smem = 4 * 512 * 4 + 2 * 256 * 24 * 4;    // 57344
            dim3 grid(N / 256, 1);
            conv_frag_kernel<256, 1, 8, 64><<<grid, 256, smem>>>(
                buf[cur], wq8 + pa.off[li], buf[dst],
                L.cin, L.cout, L.h, sh, COUTP, hwsh, wsh, alphas, scale, i);
        } else {
            int gy = COUTP / 128;
            if (N >= 256 && (N / 256) * gy >= 148) {
                size_t smem = 2 * 2048 * 4 + 2 * 256 * 24 * 4;   // 65536
                dim3 grid(N / 256, gy);
                conv_frag_kernel<256, 2, 4, 128><<<grid, 256, smem>>>(
                    buf[cur], wq8 + pa.off[li], buf[dst],
                    L.cin, L.cout, L.h, sh, COUTP, hwsh, wsh, alphas, scale, i);
            } else if (N >= 128 && (N / 128) * gy >= 148) {
                size_t smem = 2 * 2048 * 4 + 2 * 128 * 24 * 4;   // 40960
                dim3 grid(N / 128, gy);
                conv_frag_kernel<128, 2, 4, 128><<<grid, 256, smem>>>(
                    buf[cur], wq8 + pa.off[li], buf[dst],
                    L.cin, L.cout, L.h, sh, COUTP, hwsh, wsh, alphas, scale, i);
            } else {
                size_t smem = 2 * 2048 * 4 + 2 * 64 * 24 * 4;    // 28672
                dim3 grid(N / 64, gy);
                conv_frag_kernel<64, 4, 2, 128><<<grid, 256, smem>>>(
                    buf[cur], wq8 + pa.off[li], buf[dst],
                    L.cin, L.cout, L.h, sh, COUTP, hwsh, wsh, alphas, scale, i);
            }
        }
        cur = dst;
        if (L.pool_after) {
            if (i == NLAYERS - 1) {
                pool_final_kernel<<<(BATCH * 512 + 255) / 256, 256>>>(buf[cur], fc0, alphas);
            } else {
                int dst2 = 1 - cur;
                int Hout = L.h >> 1;
                int total = BATCH * Hout * Hout * L.cout;
                pool8_kernel<<<(total + 255) / 256, 256>>>(buf[cur], buf[dst2], L.cout, L.h);
                cur = dst2;
            }
        }
    }

    {
        dim3 grid1(512 / 64, BATCH / 64);
        fc64_kernel<<<grid1, 256>>>(fc0, fc1_w, fc1_b, fcA, BATCH, 512, 512, 1);
        fc64_kernel<<<grid1, 256>>>(fcA, fc2_w, fc2_b, fcB, BATCH, 512, 512, 1);
        dim3 grid3(1, BATCH / 64);
        fc64_kernel<<<grid3, 256>>>(fcB, fc3_w, fc3_b, (float*)d_out, BATCH, 10, 512, 0);
    }
}